// round 14
// baseline (speedup 1.0000x reference)
#include <cuda_runtime.h>
#include <cuda_bf16.h>
#include <math.h>
#include <stdint.h>

constexpr int NNB  = 32;
constexpr int F0   = 16;
constexpr int DD   = 256;
constexpr int NROWS = 8192;       // B*E
constexpr int NPAIRS = NROWS / 2;
constexpr int ZS   = 40;          // smem z row stride in bf16 (80B, conflict-free frags)
constexpr int WGS  = 36;          // smem WGT row stride in bf16 (72B)

// A (phase1 result) bf16 hi/lo, row-major [8192][256]
__device__ __align__(16) __nv_bfloat16 g_Ah[NROWS * DD];
__device__ __align__(16) __nv_bfloat16 g_Al[NROWS * DD];
// out_kernel^T bf16 hi/lo, row-major [n=256][k=256]  (written by phase1 CTAs 0..63)
__device__ __align__(16) __nv_bfloat16 g_WTh[DD * DD];
__device__ __align__(16) __nv_bfloat16 g_WTl[DD * DD];

// ---------------- helpers ----------------
typedef unsigned long long ull;
__device__ __forceinline__ ull pack2(float lo, float hi) {
    ull r;
    asm("mov.b64 %0, {%1, %2};" : "=l"(r) : "f"(lo), "f"(hi));
    return r;
}
__device__ __forceinline__ ull fma2(ull a, ull b, ull c) {
    ull d;
    asm("fma.rn.f32x2 %0, %1, %2, %3;" : "=l"(d) : "l"(a), "l"(b), "l"(c));
    return d;
}
__device__ __forceinline__ ull mul2(ull a, ull b) {
    ull d;
    asm("mul.rn.f32x2 %0, %1, %2;" : "=l"(d) : "l"(a), "l"(b));
    return d;
}
__device__ __forceinline__ float2 unpack2(ull v) {
    float2 r;
    asm("mov.b64 {%0, %1}, %2;" : "=f"(r.x), "=f"(r.y) : "l"(v));
    return r;
}
__device__ __forceinline__ float tanh_approx(float x) {
    float y;
    asm("tanh.approx.f32 %0, %1;" : "=f"(y) : "f"(x));
    return y;
}
__device__ __forceinline__ uint32_t smem_u32(const void* p) {
    uint32_t a;
    asm("{ .reg .u64 t; cvta.to.shared.u64 t, %1; cvt.u32.u64 %0, t; }" : "=r"(a) : "l"(p));
    return a;
}

#define MMA16816(d, a, b0v, b1v) \
    asm volatile("mma.sync.aligned.m16n8k16.row.col.f32.bf16.bf16.f32 " \
        "{%0,%1,%2,%3}, {%4,%5,%6,%7}, {%8,%9}, {%0,%1,%2,%3};" \
        : "+f"((d)[0]), "+f"((d)[1]), "+f"((d)[2]), "+f"((d)[3]) \
        : "r"((a)[0]), "r"((a)[1]), "r"((a)[2]), "r"((a)[3]), "r"(b0v), "r"(b1v))

#define CP16(daddr, sptr) \
    asm volatile("cp.async.ca.shared.global [%0], [%1], 16;" \
                 :: "r"(daddr), "l"(sptr) : "memory")

// ---------------------------------------------------------------------------
// Phase 1 (PERSISTENT, 296 CTAs): prologue computes WGT in-CTA (and CTAs 0..63
// also transpose W -> g_WTh/g_WTl for the gemm); then grid-stride over pairs.
// z hi/lo bf16, 3-chain MMA; product-reduce packed f32x2; immediate shfl.
// ---------------------------------------------------------------------------
__global__ __launch_bounds__(256, 2) void moon_phase1(
    const float* __restrict__ r,
    const float* __restrict__ r_nb,
    const float* __restrict__ ee_scales,
    const float* __restrict__ ee_kernel,
    const float* __restrict__ ee_bias,
    const float* __restrict__ dense1_kernel,
    const float* __restrict__ dense1_bias,
    const float* __restrict__ Wb,        // beta_kernel [24,32]
    const float* __restrict__ bb,        // beta_bias [32]
    const float* __restrict__ G,         // gamma_kernel [32,256]
    const float* __restrict__ W)         // out_kernel [256,256]
{
    __shared__ __align__(16) __nv_bfloat16 sZh[2][NNB][ZS];       // 5 KB
    __shared__ __align__(16) __nv_bfloat16 sZl[2][NNB][ZS];       // 5 KB
    __shared__ __align__(16) float s_inp[2][NNB][4];              // 1 KB
    __shared__ __align__(16) float s_w[4][DD];                    // 4 KB
    __shared__ __align__(16) float s_b[DD];                       // 1 KB
    __shared__ __align__(16) __nv_bfloat16 sWGh[DD * WGS];        // 18 KB
    __shared__ __align__(16) __nv_bfloat16 sWGl[DD * WGS];        // 18 KB
    __shared__ __align__(16) float s_tile[32][33];                // 4.2 KB (transpose scratch)

    const int t = threadIdx.x;

    // ---- one-time staging: dense1 ----
    #pragma unroll
    for (int i = 0; i < 4; i++) ((float*)s_w)[t + i * 256] = dense1_kernel[t + i * 256];
    s_b[t] = dense1_bias[t];

    // ---- one-time: WGT fold directly into smem (thread t = column n) ----
    {
        float gv[32];
        #pragma unroll
        for (int k = 0; k < 32; k++) gv[k] = G[k * DD + t];   // coalesced, batched
        #pragma unroll
        for (int c = 0; c < 32; c++) {
            float a = 0.0f;
            if (c < 24) {
                #pragma unroll
                for (int k = 0; k < 32; k++) a = fmaf(Wb[c * 32 + k], gv[k], a);
            } else if (c == 24) {
                #pragma unroll
                for (int k = 0; k < 32; k++) a = fmaf(bb[k], gv[k], a);
            }
            const __nv_bfloat16 h = __float2bfloat16(a);
            sWGh[t * WGS + c] = h;
            sWGl[t * WGS + c] = __float2bfloat16(a - __bfloat162float(h));
        }
    }

    // ---- one-time: CTAs 0..63 transpose W into g_WTh/g_WTl for the gemm ----
    if (blockIdx.x < 64) {
        const int bi = blockIdx.x >> 3;     // k-tile
        const int bj = blockIdx.x & 7;      // n-tile
        const int r0 = t >> 5;
        const int c  = t & 31;
        #pragma unroll
        for (int i = 0; i < 4; i++) {
            const int kr = r0 * 4 + i;
            s_tile[kr][c] = W[(bi * 32 + kr) * DD + bj * 32 + c];
        }
        __syncthreads();
        #pragma unroll
        for (int i = 0; i < 4; i++) {
            const int nr = r0 * 4 + i;
            const float w = s_tile[c][nr];
            const __nv_bfloat16 h = __float2bfloat16(w);
            const int n = bj * 32 + nr;
            const int k = bi * 32 + c;
            g_WTh[n * DD + k] = h;
            g_WTl[n * DD + k] = __float2bfloat16(w - __bfloat162float(h));
        }
    }

    const int half = t >> 7;
    const int u    = t & 127;
    const int n1   = u >> 2;          // stage1 neighbor
    const int j1   = u & 3;           // stage1 sub-thread

    const int lane = t & 31;
    const int wid  = t >> 5;
    const int gid  = lane >> 2;
    const int tig  = lane & 3;
    const int prow = wid >> 2;
    const int warpN = (wid & 3) * 64;
    const ull K05 = pack2(0.5f, 0.5f);

    __syncthreads();   // staging + WGT visible before first stage2

    for (int pair = blockIdx.x; pair < NPAIRS; pair += gridDim.x) {
        const long row = (long)pair * 2 + half;

        // ---------------- stage 1 ----------------
        {
            const int n = n1, j = j1;
            const float rx = r[row * 3 + 0];
            const float ry = r[row * 3 + 1];
            const float rz = r[row * 3 + 2];
            const float* nb = r_nb + (row * NNB + n) * 3;
            const float dx = nb[0] - rx;
            const float dy = nb[1] - ry;
            const float dz = nb[2] - rz;
            const float dist = sqrtf(dx * dx + dy * dy + dz * dz);

            const float x = dist * 0.2f;
            const float fcut = (x < 1.0f)
                ? 0.5f * (__cosf(3.14159265358979323846f * x) + 1.0f)
                : 0.0f;

            #pragma unroll
            for (int kk = 0; kk < 4; kk++) {
                const int k = j * 4 + kk;
                float a = ee_bias[k]
                        + dist * ee_kernel[0 * F0 + k]
                        + dx   * ee_kernel[1 * F0 + k]
                        + dy   * ee_kernel[2 * F0 + k]
                        + dz   * ee_kernel[3 * F0 + k];
                const float v = tanh_approx(a) * fcut;
                const __nv_bfloat16 h = __float2bfloat16(v);
                sZh[half][n][k] = h;
                sZl[half][n][k] = __float2bfloat16(v - __bfloat162float(h));
            }
            #pragma unroll
            for (int m = 0; m < 2; m++) {
                const int e = j * 2 + m;
                const float q = __fdividef(dist, ee_scales[e]);
                const float v = __expf(-q * q) * fcut;
                const __nv_bfloat16 h = __float2bfloat16(v);
                sZh[half][n][F0 + e] = h;
                sZl[half][n][F0 + e] = __float2bfloat16(v - __bfloat162float(h));
            }
            if (j == 0) {
                const uint4 z4 = make_uint4(0u, 0u, 0u, 0u);
                *(uint4*)&sZh[half][n][24] = z4;
                *(uint4*)&sZl[half][n][24] = z4;
                const __nv_bfloat16 hc = __float2bfloat16(fcut);
                sZh[half][n][24] = hc;
                sZl[half][n][24] = __float2bfloat16(fcut - __bfloat162float(hc));

                const float lp = __logf(1.0f + dist);
                const float sc = __fdividef(lp, dist);
                s_inp[half][n][0] = lp;
                s_inp[half][n][1] = dx * sc;
                s_inp[half][n][2] = dy * sc;
                s_inp[half][n][3] = dz * sc;
            }
        }
        __syncthreads();

        // ---------------- stage 2 ----------------
        {
            const long grow = (long)pair * 2 + prow;

            // A fragments (z hi/lo)
            uint32_t azh[2][2][4], azl[2][2][4];
            #pragma unroll
            for (int mf = 0; mf < 2; mf++)
                #pragma unroll
                for (int kf = 0; kf < 2; kf++) {
                    const int na = mf * 16 + gid;
                    const int nb2 = na + 8;
                    const int k  = kf * 16 + 2 * tig;
                    azh[mf][kf][0] = *(const uint32_t*)&sZh[prow][na][k];
                    azh[mf][kf][1] = *(const uint32_t*)&sZh[prow][nb2][k];
                    azh[mf][kf][2] = *(const uint32_t*)&sZh[prow][na][k + 8];
                    azh[mf][kf][3] = *(const uint32_t*)&sZh[prow][nb2][k + 8];
                    azl[mf][kf][0] = *(const uint32_t*)&sZl[prow][na][k];
                    azl[mf][kf][1] = *(const uint32_t*)&sZl[prow][nb2][k];
                    azl[mf][kf][2] = *(const uint32_t*)&sZl[prow][na][k + 8];
                    azl[mf][kf][3] = *(const uint32_t*)&sZl[prow][nb2][k + 8];
                }

            // hoisted ip packs
            ull ipp[4][4];
            #pragma unroll
            for (int it = 0; it < 4; it++) {
                const int n = ((it >> 1) * 16) + ((it & 1) * 8) + gid;
                const float4 ip = *(const float4*)s_inp[prow][n];
                ipp[it][0] = pack2(ip.x, ip.x);
                ipp[it][1] = pack2(ip.y, ip.y);
                ipp[it][2] = pack2(ip.z, ip.z);
                ipp[it][3] = pack2(ip.w, ip.w);
            }

            #pragma unroll
            for (int hn = 0; hn < 2; hn++) {
                float acc[2][4][4];
                #pragma unroll
                for (int mf = 0; mf < 2; mf++)
                    #pragma unroll
                    for (int nf = 0; nf < 4; nf++)
                        #pragma unroll
                        for (int c = 0; c < 4; c++) acc[mf][nf][c] = 0.0f;

                #pragma unroll
                for (int nf = 0; nf < 4; nf++) {
                    const int ncol = warpN + hn * 32 + nf * 8 + gid;
                    const __nv_bfloat16* ph = &sWGh[ncol * WGS];
                    const __nv_bfloat16* pl = &sWGl[ncol * WGS];
                    #pragma unroll
                    for (int kf = 0; kf < 2; kf++) {
                        const uint32_t bh0 = *(const uint32_t*)&ph[kf * 16 + 2 * tig];
                        const uint32_t bh1 = *(const uint32_t*)&ph[kf * 16 + 8 + 2 * tig];
                        const uint32_t bl0 = *(const uint32_t*)&pl[kf * 16 + 2 * tig];
                        const uint32_t bl1 = *(const uint32_t*)&pl[kf * 16 + 8 + 2 * tig];
                        MMA16816(acc[0][nf], azh[0][kf], bh0, bh1);
                        MMA16816(acc[1][nf], azh[1][kf], bh0, bh1);
                        MMA16816(acc[0][nf], azh[0][kf], bl0, bl1);
                        MMA16816(acc[1][nf], azh[1][kf], bl0, bl1);
                        MMA16816(acc[0][nf], azl[0][kf], bh0, bh1);
                        MMA16816(acc[1][nf], azl[1][kf], bh0, bh1);
                    }
                }

                // packed product-reduce, immediate shfl per nf
                #pragma unroll
                for (int nf = 0; nf < 4; nf++) {
                    const int d0 = warpN + hn * 32 + nf * 8 + 2 * tig;
                    const ull wp0 = *(const ull*)&s_w[0][d0];
                    const ull wp1 = *(const ull*)&s_w[1][d0];
                    const ull wp2 = *(const ull*)&s_w[2][d0];
                    const ull wp3 = *(const ull*)&s_w[3][d0];
                    const ull bp  = *(const ull*)&s_b[d0];

                    ull s2 = 0ull;
                    #pragma unroll
                    for (int it = 0; it < 4; it++) {
                        ull pre2 = fma2(ipp[it][0], wp0,
                                   fma2(ipp[it][1], wp1,
                                   fma2(ipp[it][2], wp2,
                                   fma2(ipp[it][3], wp3, bp))));
                        const ull ph2 = mul2(pre2, K05);
                        const float2 pu = unpack2(ph2);
                        const ull tp = pack2(tanh_approx(pu.x), tanh_approx(pu.y));
                        const ull sg = fma2(tp, K05, K05);
                        const ull feat2 = mul2(pre2, sg);
                        const ull gam2 = pack2(acc[it >> 1][nf][(it & 1) * 2],
                                               acc[it >> 1][nf][(it & 1) * 2 + 1]);
                        s2 = fma2(feat2, gam2, s2);
                    }

                    float2 sv = unpack2(s2);
                    sv.x += __shfl_xor_sync(0xffffffffu, sv.x, 4);
                    sv.y += __shfl_xor_sync(0xffffffffu, sv.y, 4);
                    sv.x += __shfl_xor_sync(0xffffffffu, sv.x, 8);
                    sv.y += __shfl_xor_sync(0xffffffffu, sv.y, 8);
                    sv.x += __shfl_xor_sync(0xffffffffu, sv.x, 16);
                    sv.y += __shfl_xor_sync(0xffffffffu, sv.y, 16);

                    if (gid == 0) {
                        const __nv_bfloat16 h0 = __float2bfloat16(sv.x);
                        const __nv_bfloat16 h1 = __float2bfloat16(sv.y);
                        *(__nv_bfloat162*)&g_Ah[grow * DD + d0] = __halves2bfloat162(h0, h1);
                        const __nv_bfloat16 l0 = __float2bfloat16(sv.x - __bfloat162float(h0));
                        const __nv_bfloat16 l1 = __float2bfloat16(sv.y - __bfloat162float(h1));
                        *(__nv_bfloat162*)&g_Al[grow * DD + d0] = __halves2bfloat162(l0, l1);
                    }
                }
            }
        }
        __syncthreads();   // protect sZ/s_inp before next iteration overwrites
    }
}

// ---------------------------------------------------------------------------
// Kernel B: Y = silu(A @ W + bias), 3-chain compensated bf16,
// cp.async 2-stage pipelined K chunks.
// ---------------------------------------------------------------------------
constexpr int KS = 88;
constexpr int TILE_BYTES = 128 * KS * 2;       // 22528
constexpr int STAGE_BYTES = 4 * TILE_BYTES;    // 90112

__global__ __launch_bounds__(256) void moon_gemm_mma(
    const float* __restrict__ bias, float* __restrict__ Y)
{
    extern __shared__ __align__(16) char smem[];

    const int t    = threadIdx.x;
    const int lane = t & 31;
    const int wid  = t >> 5;
    const int gid  = lane >> 2;
    const int tig  = lane & 3;
    const int warp_m = wid & 3;
    const int warp_n = wid >> 2;
    const int ct   = blockIdx.x;
    const int rowT = blockIdx.y;

    const uint32_t sbase = smem_u32(smem);

    float acc[2][8][4];
    #pragma unroll
    for (int mf = 0; mf < 2; mf++)
        #pragma unroll
        for (int j = 0; j < 8; j++)
            #pragma unroll
            for (int c = 0; c < 4; c++) acc[mf][j][c] = 0.0f;

    const size_t aBase = (size_t)(rowT * 128) * DD;
    const size_t bBase = (size_t)(ct * 128) * DD;

    #define ISSUE_STAGE(kc, sidx) do { \
        const uint32_t sb_ = sbase + (sidx) * STAGE_BYTES; \
        _Pragma("unroll") \
        for (int i_ = 0; i_ < 4; i_++) { \
            const int lin_ = t + i_ * 256; \
            const int rr_  = lin_ >> 3; \
            const int kq_  = (lin_ & 7) * 8; \
            const size_t goff_ = (size_t)rr_ * DD + (kc) * 64 + kq_; \
            const uint32_t so_ = (uint32_t)(rr_ * KS + kq_) * 2; \
            CP16(sb_ + so_,                  &g_Ah[aBase + goff_]); \
            CP16(sb_ + TILE_BYTES + so_,     &g_Al[aBase + goff_]); \
            CP16(sb_ + 2 * TILE_BYTES + so_, &g_WTh[bBase + goff_]); \
            CP16(sb_ + 3 * TILE_BYTES + so_, &g_WTl[bBase + goff_]); \
        } \
        asm volatile("cp.async.commit_group;" ::: "memory"); \
    } while (0)

    ISSUE_STAGE(0, 0);
    ISSUE_STAGE(1, 1);

    #pragma unroll
    for (int kc = 0; kc < 4; kc++) {
        if (kc < 3) asm volatile("cp.async.wait_group 1;" ::: "memory");
        else        asm volatile("cp.async.wait_group 0;" ::: "memory");
        __syncthreads();

        const int sidx = kc & 1;
        const __nv_bfloat16* sAh = (const __nv_bfloat16*)(smem + sidx * STAGE_BYTES);
        const __nv_bfloat16* sAl = (const __nv_bfloat16*)(smem + sidx * STAGE_BYTES + TILE_BYTES);
        const __nv_bfloat16* sBh = (const __nv_bfloat16*)(smem + sidx * STAGE_BYTES + 2 * TILE_BYTES);
        const __nv_bfloat16* sBl = (const __nv_bfloat16*)(smem + sidx * STAGE_BYTES + 3 * TILE_BYTES);

        #pragma unroll
        for (int k16 = 0; k16 < 4; k16++) {
            const int koff = k16 * 16;
            uint32_t ah[2][4], al[2][4];
            #pragma unroll
            for (int mf = 0; mf < 2; mf++) {
                const int mb = warp_m * 32 + mf * 16;
                const int r0 = (mb + gid) * KS + koff + 2 * tig;
                const int r1 = (mb + 8 + gid) * KS + koff + 2 * tig;
                ah[mf][0] = *(const uint32_t*)&sAh[r0];
                ah[mf][1] = *(const uint32_t*)&sAh[r1];
                ah[mf][2] = *(const uint32_t*)&sAh[r0 + 8];
                ah[mf][3] = *(const uint32_t*)&sAh[r1 + 8];
                al[mf][0] = *(const uint32_t*)&sAl[r0];
                al[mf][1] = *(const uint32_t*)&sAl[r1];
                al[mf][2] = *(const uint32_t*)&sAl[r0 + 8];
                al[mf][3] = *(const uint32_t*)&sAl[r1 + 8];
            }
            #pragma unroll
            for (int j = 0; j < 8; j++) {
                const int nb = (warp_n * 64 + j * 8 + gid) * KS + koff + 2 * tig;
                const uint32_t bh0 = *(const uint32_t*)&sBh[nb];
                const uint32_t bh1 = *(const uint32_t*)&sBh[nb + 8];
                const uint32_t bl0 = *(const uint32_t*)&sBl[nb];
                const uint32_t bl1 = *(const uint32_t*)&sBl[nb + 8];
                #pragma unroll
                for (int mf = 0; mf < 2; mf++) {
                    MMA16816(acc[mf][j], ah[mf], bh0, bh1);
                    MMA16816(acc[mf][j], ah[mf], bl0, bl1);
                    MMA16816(acc[mf][j], al[mf], bh0, bh1);
                }
            }
        }
        __syncthreads();
        if (kc < 2) ISSUE_STAGE(kc + 2, sidx);
    }

    #pragma unroll
    for (int j = 0; j < 8; j++) {
        const int col = ct * 128 + warp_n * 64 + j * 8 + 2 * tig;
        const float2 bb = *(const float2*)&bias[col];
        #pragma unroll
        for (int mf = 0; mf < 2; mf++) {
            const long row0 = rowT * 128 + warp_m * 32 + mf * 16 + gid;
            float v0 = acc[mf][j][0] + bb.x;
            float v1 = acc[mf][j][1] + bb.y;
            float v2 = acc[mf][j][2] + bb.x;
            float v3 = acc[mf][j][3] + bb.y;
            float2 o0, o1;
            o0.x = __fdividef(v0, 1.0f + __expf(-v0));
            o0.y = __fdividef(v1, 1.0f + __expf(-v1));
            o1.x = __fdividef(v2, 1.0f + __expf(-v2));
            o1.y = __fdividef(v3, 1.0f + __expf(-v3));
            *(float2*)&Y[row0 * DD + col]       = o0;
            *(float2*)&Y[(row0 + 8) * DD + col] = o1;
        }
    }
}

// ---------------------------------------------------------------------------
extern "C" void kernel_launch(void* const* d_in, const int* in_sizes, int n_in,
                              void* d_out, int out_size)
{
    const float* r             = (const float*)d_in[0];
    const float* r_nb          = (const float*)d_in[1];
    const float* ee_scales     = (const float*)d_in[2];
    const float* ee_kernel     = (const float*)d_in[3];
    const float* ee_bias       = (const float*)d_in[4];
    const float* beta_kernel   = (const float*)d_in[5];
    const float* beta_bias     = (const float*)d_in[6];
    const float* gamma_kernel  = (const float*)d_in[7];
    const float* dense1_kernel = (const float*)d_in[8];
    const float* dense1_bias   = (const float*)d_in[9];
    const float* out_kernel    = (const float*)d_in[10];
    const float* out_bias      = (const float*)d_in[11];

    static bool attr_done = false;
    if (!attr_done) {
        cudaFuncSetAttribute(moon_gemm_mma,
                             cudaFuncAttributeMaxDynamicSharedMemorySize,
                             2 * STAGE_BYTES);
        attr_done = true;
    }

    moon_phase1<<<296, 256>>>(r, r_nb, ee_scales, ee_kernel, ee_bias,
                              dense1_kernel, dense1_bias,
                              beta_kernel, beta_bias, gamma_kernel, out_kernel);

    dim3 gridB(2, NROWS / 128);
    moon_gemm_mma<<<gridB, 256, 2 * STAGE_BYTES>>>(out_bias, (float*)d_out);
}

// round 15
// speedup vs baseline: 1.0018x; 1.0018x over previous
#include <cuda_runtime.h>
#include <cuda_bf16.h>
#include <math.h>
#include <stdint.h>

constexpr int NNB  = 32;
constexpr int F0   = 16;
constexpr int DD   = 256;
constexpr int NROWS = 8192;       // B*E
constexpr int NPAIRS = NROWS / 2;
constexpr int ZS   = 40;          // smem z row stride in bf16 (80B, conflict-free frags)
constexpr int WGS  = 36;          // smem WGT row stride in bf16 (72B)

// A (phase1 result) bf16 hi/lo, row-major [8192][256]
__device__ __align__(16) __nv_bfloat16 g_Ah[NROWS * DD];
__device__ __align__(16) __nv_bfloat16 g_Al[NROWS * DD];
// out_kernel^T bf16 hi/lo, row-major [n=256][k=256]
__device__ __align__(16) __nv_bfloat16 g_WTh[DD * DD];
__device__ __align__(16) __nv_bfloat16 g_WTl[DD * DD];
// WG^T = (fold of beta_kernel/bias @ gamma)^T, bf16 hi/lo, [d=256][c=32] (c>=25 zero)
__device__ __align__(16) __nv_bfloat16 g_WGTh[DD * 32];
__device__ __align__(16) __nv_bfloat16 g_WGTl[DD * 32];

// ---------------- helpers ----------------
typedef unsigned long long ull;
__device__ __forceinline__ ull pack2(float lo, float hi) {
    ull r;
    asm("mov.b64 %0, {%1, %2};" : "=l"(r) : "f"(lo), "f"(hi));
    return r;
}
__device__ __forceinline__ ull fma2(ull a, ull b, ull c) {
    ull d;
    asm("fma.rn.f32x2 %0, %1, %2, %3;" : "=l"(d) : "l"(a), "l"(b), "l"(c));
    return d;
}
__device__ __forceinline__ ull mul2(ull a, ull b) {
    ull d;
    asm("mul.rn.f32x2 %0, %1, %2;" : "=l"(d) : "l"(a), "l"(b));
    return d;
}
__device__ __forceinline__ float2 unpack2(ull v) {
    float2 r;
    asm("mov.b64 {%0, %1}, %2;" : "=f"(r.x), "=f"(r.y) : "l"(v));
    return r;
}
__device__ __forceinline__ float tanh_approx(float x) {
    float y;
    asm("tanh.approx.f32 %0, %1;" : "=f"(y) : "f"(x));
    return y;
}
__device__ __forceinline__ uint32_t smem_u32(const void* p) {
    uint32_t a;
    asm("{ .reg .u64 t; cvta.to.shared.u64 t, %1; cvt.u32.u64 %0, t; }" : "=r"(a) : "l"(p));
    return a;
}

#define MMA16816(d, a, b0v, b1v) \
    asm volatile("mma.sync.aligned.m16n8k16.row.col.f32.bf16.bf16.f32 " \
        "{%0,%1,%2,%3}, {%4,%5,%6,%7}, {%8,%9}, {%0,%1,%2,%3};" \
        : "+f"((d)[0]), "+f"((d)[1]), "+f"((d)[2]), "+f"((d)[3]) \
        : "r"((a)[0]), "r"((a)[1]), "r"((a)[2]), "r"((a)[3]), "r"(b0v), "r"(b1v))

#define CP16(daddr, sptr) \
    asm volatile("cp.async.ca.shared.global [%0], [%1], 16;" \
                 :: "r"(daddr), "l"(sptr) : "memory")

// ---------------------------------------------------------------------------
// Setup: blocks 0..63: 32x32 tiled transpose of W (coalesced both sides).
//        blocks 64..71: WG fold, fully unrolled k-loop (batched LDGs, MLP=32).
// ---------------------------------------------------------------------------
__global__ void moon_setup(const float* __restrict__ Wb,   // [24,32]
                           const float* __restrict__ bb,   // [32]
                           const float* __restrict__ G,    // [32,256]
                           const float* __restrict__ W)    // [256,256]
{
    const int b = blockIdx.x;
    const int t = threadIdx.x;
    if (b < 64) {
        __shared__ float tile[32][33];
        const int bi = b >> 3;          // k-tile of W rows
        const int bj = b & 7;           // n-tile of W cols
        const int r0 = t >> 5;          // 0..7
        const int c  = t & 31;
        #pragma unroll
        for (int i = 0; i < 4; i++) {
            const int kr = r0 * 4 + i;
            tile[kr][c] = W[(bi * 32 + kr) * DD + bj * 32 + c];   // coalesced read
        }
        __syncthreads();
        #pragma unroll
        for (int i = 0; i < 4; i++) {
            const int nr = r0 * 4 + i;
            const float w = tile[c][nr];  // = W[bi*32+c][bj*32+nr]
            const __nv_bfloat16 h = __float2bfloat16(w);
            const int n = bj * 32 + nr;
            const int k = bi * 32 + c;
            g_WTh[n * DD + k] = h;                                 // coalesced store
            g_WTl[n * DD + k] = __float2bfloat16(w - __bfloat162float(h));
        }
    } else {
        const int b2 = b - 64;                 // 0..7
        const int n  = b2 * 32 + (t & 31);
        const int cg = t >> 5;                 // 0..7 -> c = cg*4..cg*4+3
        float a[4] = {0.0f, 0.0f, 0.0f, 0.0f};
        #pragma unroll
        for (int k = 0; k < 32; k++) {
            const float g = G[k * DD + n];     // 32 independent batched loads
            #pragma unroll
            for (int q = 0; q < 4; q++) {
                const int c = cg * 4 + q;
                const float wv = (c < 24) ? Wb[c * 32 + k]
                                          : ((c == 24) ? bb[k] : 0.0f);
                a[q] = fmaf(wv, g, a[q]);
            }
        }
        #pragma unroll
        for (int q = 0; q < 4; q++) {
            const int c = cg * 4 + q;
            const __nv_bfloat16 h = __float2bfloat16(a[q]);
            g_WGTh[n * 32 + c] = h;
            g_WGTl[n * 32 + c] = __float2bfloat16(a[q] - __bfloat162float(h));
        }
    }
}

// ---------------------------------------------------------------------------
// Phase 1 (PERSISTENT): 296 CTAs, grid-stride over 4096 row-pairs.
// WGT/dense1 staged into smem ONCE per CTA; loop body = stage1 + stage2.
// z hi/lo bf16, 3-chain MMA; product-reduce packed f32x2; immediate shfl.
// ---------------------------------------------------------------------------
__global__ __launch_bounds__(256, 2) void moon_phase1(
    const float* __restrict__ r,
    const float* __restrict__ r_nb,
    const float* __restrict__ ee_scales,
    const float* __restrict__ ee_kernel,
    const float* __restrict__ ee_bias,
    const float* __restrict__ dense1_kernel,
    const float* __restrict__ dense1_bias)
{
    __shared__ __align__(16) __nv_bfloat16 sZh[2][NNB][ZS];       // 5 KB
    __shared__ __align__(16) __nv_bfloat16 sZl[2][NNB][ZS];       // 5 KB
    __shared__ __align__(16) float s_inp[2][NNB][4];              // 1 KB
    __shared__ __align__(16) float s_w[4][DD];                    // 4 KB
    __shared__ __align__(16) float s_b[DD];                       // 1 KB
    __shared__ __align__(16) __nv_bfloat16 sWGh[DD * WGS];        // 18 KB
    __shared__ __align__(16) __nv_bfloat16 sWGl[DD * WGS];        // 18 KB

    const int t = threadIdx.x;

    // ---- one-time staging ----
    #pragma unroll
    for (int i = 0; i < 4; i++) ((float*)s_w)[t + i * 256] = dense1_kernel[t + i * 256];
    s_b[t] = dense1_bias[t];
    {
        const uint2* srcH = (const uint2*)&g_WGTh[t * 32];
        const uint2* srcL = (const uint2*)&g_WGTl[t * 32];
        uint2* dstH = (uint2*)&sWGh[t * WGS];
        uint2* dstL = (uint2*)&sWGl[t * WGS];
        #pragma unroll
        for (int i = 0; i < 8; i++) { dstH[i] = srcH[i]; dstL[i] = srcL[i]; }
    }

    const int half = t >> 7;
    const int u    = t & 127;
    const int n1   = u >> 2;          // stage1 neighbor
    const int j1   = u & 3;           // stage1 sub-thread

    const int lane = t & 31;
    const int wid  = t >> 5;
    const int gid  = lane >> 2;
    const int tig  = lane & 3;
    const int prow = wid >> 2;
    const int warpN = (wid & 3) * 64;
    const ull K05 = pack2(0.5f, 0.5f);

    __syncthreads();   // staging visible before first stage2

    for (int pair = blockIdx.x; pair < NPAIRS; pair += gridDim.x) {
        const long row = (long)pair * 2 + half;

        // ---------------- stage 1 ----------------
        {
            const int n = n1, j = j1;
            const float rx = r[row * 3 + 0];
            const float ry = r[row * 3 + 1];
            const float rz = r[row * 3 + 2];
            const float* nb = r_nb + (row * NNB + n) * 3;
            const float dx = nb[0] - rx;
            const float dy = nb[1] - ry;
            const float dz = nb[2] - rz;
            const float dist = sqrtf(dx * dx + dy * dy + dz * dz);

            const float x = dist * 0.2f;
            const float fcut = (x < 1.0f)
                ? 0.5f * (__cosf(3.14159265358979323846f * x) + 1.0f)
                : 0.0f;

            #pragma unroll
            for (int kk = 0; kk < 4; kk++) {
                const int k = j * 4 + kk;
                float a = ee_bias[k]
                        + dist * ee_kernel[0 * F0 + k]
                        + dx   * ee_kernel[1 * F0 + k]
                        + dy   * ee_kernel[2 * F0 + k]
                        + dz   * ee_kernel[3 * F0 + k];
                const float v = tanh_approx(a) * fcut;
                const __nv_bfloat16 h = __float2bfloat16(v);
                sZh[half][n][k] = h;
                sZl[half][n][k] = __float2bfloat16(v - __bfloat162float(h));
            }
            #pragma unroll
            for (int m = 0; m < 2; m++) {
                const int e = j * 2 + m;
                const float q = __fdividef(dist, ee_scales[e]);
                const float v = __expf(-q * q) * fcut;
                const __nv_bfloat16 h = __float2bfloat16(v);
                sZh[half][n][F0 + e] = h;
                sZl[half][n][F0 + e] = __float2bfloat16(v - __bfloat162float(h));
            }
            if (j == 0) {
                const uint4 z4 = make_uint4(0u, 0u, 0u, 0u);
                *(uint4*)&sZh[half][n][24] = z4;
                *(uint4*)&sZl[half][n][24] = z4;
                const __nv_bfloat16 hc = __float2bfloat16(fcut);
                sZh[half][n][24] = hc;
                sZl[half][n][24] = __float2bfloat16(fcut - __bfloat162float(hc));

                const float lp = __logf(1.0f + dist);
                const float sc = __fdividef(lp, dist);
                s_inp[half][n][0] = lp;
                s_inp[half][n][1] = dx * sc;
                s_inp[half][n][2] = dy * sc;
                s_inp[half][n][3] = dz * sc;
            }
        }
        __syncthreads();

        // ---------------- stage 2 ----------------
        {
            const long grow = (long)pair * 2 + prow;

            // A fragments (z hi/lo)
            uint32_t azh[2][2][4], azl[2][2][4];
            #pragma unroll
            for (int mf = 0; mf < 2; mf++)
                #pragma unroll
                for (int kf = 0; kf < 2; kf++) {
                    const int na = mf * 16 + gid;
                    const int nb2 = na + 8;
                    const int k  = kf * 16 + 2 * tig;
                    azh[mf][kf][0] = *(const uint32_t*)&sZh[prow][na][k];
                    azh[mf][kf][1] = *(const uint32_t*)&sZh[prow][nb2][k];
                    azh[mf][kf][2] = *(const uint32_t*)&sZh[prow][na][k + 8];
                    azh[mf][kf][3] = *(const uint32_t*)&sZh[prow][nb2][k + 8];
                    azl[mf][kf][0] = *(const uint32_t*)&sZl[prow][na][k];
                    azl[mf][kf][1] = *(const uint32_t*)&sZl[prow][nb2][k];
                    azl[mf][kf][2] = *(const uint32_t*)&sZl[prow][na][k + 8];
                    azl[mf][kf][3] = *(const uint32_t*)&sZl[prow][nb2][k + 8];
                }

            // hoisted ip packs
            ull ipp[4][4];
            #pragma unroll
            for (int it = 0; it < 4; it++) {
                const int n = ((it >> 1) * 16) + ((it & 1) * 8) + gid;
                const float4 ip = *(const float4*)s_inp[prow][n];
                ipp[it][0] = pack2(ip.x, ip.x);
                ipp[it][1] = pack2(ip.y, ip.y);
                ipp[it][2] = pack2(ip.z, ip.z);
                ipp[it][3] = pack2(ip.w, ip.w);
            }

            #pragma unroll
            for (int hn = 0; hn < 2; hn++) {
                float acc[2][4][4];
                #pragma unroll
                for (int mf = 0; mf < 2; mf++)
                    #pragma unroll
                    for (int nf = 0; nf < 4; nf++)
                        #pragma unroll
                        for (int c = 0; c < 4; c++) acc[mf][nf][c] = 0.0f;

                #pragma unroll
                for (int nf = 0; nf < 4; nf++) {
                    const int ncol = warpN + hn * 32 + nf * 8 + gid;
                    const __nv_bfloat16* ph = &sWGh[ncol * WGS];
                    const __nv_bfloat16* pl = &sWGl[ncol * WGS];
                    #pragma unroll
                    for (int kf = 0; kf < 2; kf++) {
                        const uint32_t bh0 = *(const uint32_t*)&ph[kf * 16 + 2 * tig];
                        const uint32_t bh1 = *(const uint32_t*)&ph[kf * 16 + 8 + 2 * tig];
                        const uint32_t bl0 = *(const uint32_t*)&pl[kf * 16 + 2 * tig];
                        const uint32_t bl1 = *(const uint32_t*)&pl[kf * 16 + 8 + 2 * tig];
                        MMA16816(acc[0][nf], azh[0][kf], bh0, bh1);
                        MMA16816(acc[1][nf], azh[1][kf], bh0, bh1);
                        MMA16816(acc[0][nf], azh[0][kf], bl0, bl1);
                        MMA16816(acc[1][nf], azh[1][kf], bl0, bl1);
                        MMA16816(acc[0][nf], azl[0][kf], bh0, bh1);
                        MMA16816(acc[1][nf], azl[1][kf], bh0, bh1);
                    }
                }

                // packed product-reduce, immediate shfl per nf
                #pragma unroll
                for (int nf = 0; nf < 4; nf++) {
                    const int d0 = warpN + hn * 32 + nf * 8 + 2 * tig;
                    const ull wp0 = *(const ull*)&s_w[0][d0];
                    const ull wp1 = *(const ull*)&s_w[1][d0];
                    const ull wp2 = *(const ull*)&s_w[2][d0];
                    const ull wp3 = *(const ull*)&s_w[3][d0];
                    const ull bp  = *(const ull*)&s_b[d0];

                    ull s2 = 0ull;
                    #pragma unroll
                    for (int it = 0; it < 4; it++) {
                        ull pre2 = fma2(ipp[it][0], wp0,
                                   fma2(ipp[it][1], wp1,
                                   fma2(ipp[it][2], wp2,
                                   fma2(ipp[it][3], wp3, bp))));
                        const ull ph2 = mul2(pre2, K05);
                        const float2 pu = unpack2(ph2);
                        const ull tp = pack2(tanh_approx(pu.x), tanh_approx(pu.y));
                        const ull sg = fma2(tp, K05, K05);
                        const ull feat2 = mul2(pre2, sg);
                        const ull gam2 = pack2(acc[it >> 1][nf][(it & 1) * 2],
                                               acc[it >> 1][nf][(it & 1) * 2 + 1]);
                        s2 = fma2(feat2, gam2, s2);
                    }

                    float2 sv = unpack2(s2);
                    sv.x += __shfl_xor_sync(0xffffffffu, sv.x, 4);
                    sv.y += __shfl_xor_sync(0xffffffffu, sv.y, 4);
                    sv.x += __shfl_xor_sync(0xffffffffu, sv.x, 8);
                    sv.y += __shfl_xor_sync(0xffffffffu, sv.y, 8);
                    sv.x += __shfl_xor_sync(0xffffffffu, sv.x, 16);
                    sv.y += __shfl_xor_sync(0xffffffffu, sv.y, 16);

                    if (gid == 0) {
                        const __nv_bfloat16 h0 = __float2bfloat16(sv.x);
                        const __nv_bfloat16 h1 = __float2bfloat16(sv.y);
                        *(__nv_bfloat162*)&g_Ah[grow * DD + d0] = __halves2bfloat162(h0, h1);
                        const __nv_bfloat16 l0 = __float2bfloat16(sv.x - __bfloat162float(h0));
                        const __nv_bfloat16 l1 = __float2bfloat16(sv.y - __bfloat162float(h1));
                        *(__nv_bfloat162*)&g_Al[grow * DD + d0] = __halves2bfloat162(l0, l1);
                    }
                }
            }
        }
        __syncthreads();   // protect sZ/s_inp before next iteration overwrites
    }
}

// ---------------------------------------------------------------------------
// Kernel B: Y = silu(A @ W + bias), 3-chain compensated bf16.
// BM=128, BN=64, KS=72; 2-stage cp.async; 2 CTAs/SM (108 KB smem/CTA).
// 8 warps = 4M x 2N.
// ---------------------------------------------------------------------------
constexpr int KS = 72;                      // k stride in bf16 (144B rows)
constexpr int TILE_A = 128 * KS * 2;        // 18432 B  (one of Ah / Al)
constexpr int TILE_B = 64 * KS * 2;         // 9216 B   (one of Bh / Bl)
constexpr int OFF_AL = TILE_A;              // 18432
constexpr int OFF_BH = 2 * TILE_A;          // 36864
constexpr int OFF_BL = 2 * TILE_A + TILE_B; // 46080
constexpr int STAGE_BYTES = 2 * TILE_A + 2 * TILE_B;  // 55296

__global__ __launch_bounds__(256, 2) void moon_gemm_mma(
    const float* __restrict__ bias, float* __restrict__ Y)
{
    extern __shared__ __align__(16) char smem[];

    const int t    = threadIdx.x;
    const int lane = t & 31;
    const int wid  = t >> 5;
    const int gid  = lane >> 2;
    const int tig  = lane & 3;
    const int warp_m = wid & 3;     // 4 M-warps (32 rows each)
    const int warp_n = wid >> 2;    // 2 N-warps (32 cols each)
    const int ct   = blockIdx.x;    // 0..3  (64-col tile)
    const int rowT = blockIdx.y;    // 0..63

    const uint32_t sbase = smem_u32(smem);

    float acc[2][4][4];
    #pragma unroll
    for (int mf = 0; mf < 2; mf++)
        #pragma unroll
        for (int j = 0; j < 4; j++)
            #pragma unroll
            for (int c = 0; c < 4; c++) acc[mf][j][c] = 0.0f;

    const size_t aBase = (size_t)(rowT * 128) * DD;
    const size_t bBase = (size_t)(ct * 64) * DD;

    #define ISSUE_STAGE(kc, sidx) do { \
        const uint32_t sb_ = sbase + (sidx) * STAGE_BYTES; \
        _Pragma("unroll") \
        for (int i_ = 0; i_ < 4; i_++) { \
            const int lin_ = t + i_ * 256; \
            const int rr_  = lin_ >> 3; \
            const int kq_  = (lin_ & 7) * 8; \
            const size_t goff_ = (size_t)rr_ * DD + (kc) * 64 + kq_; \
            const uint32_t so_ = (uint32_t)(rr_ * KS + kq_) * 2; \
            CP16(sb_ + so_,          &g_Ah[aBase + goff_]); \
            CP16(sb_ + OFF_AL + so_, &g_Al[aBase + goff_]); \
        } \
        _Pragma("unroll") \
        for (int i_ = 0; i_ < 2; i_++) { \
            const int lin_ = t + i_ * 256; \
            const int rr_  = lin_ >> 3; \
            const int kq_  = (lin_ & 7) * 8; \
            const size_t goff_ = (size_t)rr_ * DD + (kc) * 64 + kq_; \
            const uint32_t so_ = (uint32_t)(rr_ * KS + kq_) * 2; \
            CP16(sb_ + OFF_BH + so_, &g_WTh[bBase + goff_]); \
            CP16(sb_ + OFF_BL + so_, &g_WTl[bBase + goff_]); \
        } \
        asm volatile("cp.async.commit_group;" ::: "memory"); \
    } while (0)

    ISSUE_STAGE(0, 0);
    ISSUE_STAGE(1, 1);

    #pragma unroll
    for (int kc = 0; kc < 4; kc++) {
        if (kc < 3) asm volatile("cp.async.wait_group 1;" ::: "memory");
        else        asm volatile("cp.async.wait_group 0;" ::: "memory");
        __syncthreads();

        const int sidx = kc & 1;
        const __nv_bfloat16* sAh = (const __nv_bfloat16*)(smem + sidx * STAGE_BYTES);
        const __nv_bfloat16* sAl = (const __nv_bfloat16*)(smem + sidx * STAGE_BYTES + OFF_AL);
        const __nv_bfloat16* sBh = (const __nv_bfloat16*)(smem + sidx * STAGE_BYTES + OFF_BH);
        const __nv_bfloat16* sBl = (const __nv_bfloat16*)(smem + sidx * STAGE_BYTES + OFF_BL);

        #pragma unroll
        for (int k16 = 0; k16 < 4; k16++) {
            const int koff = k16 * 16;
            uint32_t ah[2][4], al[2][4];
            #pragma unroll
            for (int mf = 0; mf < 2; mf++) {
                const int mb = warp_m * 32 + mf * 16;
                const int r0 = (mb + gid) * KS + koff + 2 * tig;
                const int r1 = (mb + 8 + gid) * KS + koff + 2 * tig;
                ah[mf][0] = *(const uint32_t*)&sAh[r0];
                ah[mf][1] = *(const uint32_t*)&sAh[r1];
                ah[mf][2] = *(const uint32_t*)&sAh[r0 + 8];
                ah[mf][3] = *(const uint32_t*)&sAh[r1 + 8];
                al[mf][0] = *(const uint32_t*)&sAl[r0];
                al[mf][1] = *(const uint32_t*)&sAl[r1];
                al[mf][2] = *(const uint32_t*)&sAl[r0 + 8];
                al[mf][3] = *(const uint32_t*)&sAl[r1 + 8];
            }
            #pragma unroll
            for (int j = 0; j < 4; j++) {
                const int nb = (warp_n * 32 + j * 8 + gid) * KS + koff + 2 * tig;
                const uint32_t bh0 = *(const uint32_t*)&sBh[nb];
                const uint32_t bh1 = *(const uint32_t*)&sBh[nb + 8];
                const uint32_t bl0 = *(const uint32_t*)&sBl[nb];
                const uint32_t bl1 = *(const uint32_t*)&sBl[nb + 8];
                #pragma unroll
                for (int mf = 0; mf < 2; mf++) {
                    MMA16816(acc[mf][j], ah[mf], bh0, bh1);
                    MMA16816(acc[mf][j], ah[mf], bl0, bl1);
                    MMA16816(acc[mf][j], al[mf], bh0, bh1);
                }
            }
        }
        __syncthreads();
        if (kc < 2) ISSUE_STAGE(kc + 2, sidx);
    }

    #pragma unroll
    for (int j = 0; j < 4; j++) {
        const int col = ct * 64 + warp_n * 32 + j * 8 + 2 * tig;
        const float2 bb = *(const float2*)&bias[col];
        #pragma unroll
        for (int mf = 0; mf < 2; mf++) {
            const long row0 = rowT * 128 + warp_m * 32 + mf * 16 + gid;
            float v0 = acc[mf][j][0] + bb.x;
            float v1 = acc[mf][j][1] + bb.y;
            float v2 = acc[mf][j][2] + bb.x;
            float v3 = acc[mf][j][3] + bb.y;
            float2 o0, o1;
            o0.x = __fdividef(v0, 1.0f + __expf(-v0));
            o0.y = __fdividef(v1, 1.0f + __expf(-v1));
            o1.x = __fdividef(v2, 1.0f + __expf(-v2));
            o1.y = __fdividef(v3, 1.0f + __expf(-v3));
            *(float2*)&Y[row0 * DD + col]       = o0;
            *(float2*)&Y[(row0 + 8) * DD + col] = o1;
        }
    }
}

// ---------------------------------------------------------------------------
extern "C" void kernel_launch(void* const* d_in, const int* in_sizes, int n_in,
                              void* d_out, int out_size)
{
    const float* r             = (const float*)d_in[0];
    const float* r_nb          = (const float*)d_in[1];
    const float* ee_scales     = (const float*)d_in[2];
    const float* ee_kernel     = (const float*)d_in[3];
    const float* ee_bias       = (const float*)d_in[4];
    const float* beta_kernel   = (const float*)d_in[5];
    const float* beta_bias     = (const float*)d_in[6];
    const float* gamma_kernel  = (const float*)d_in[7];
    const float* dense1_kernel = (const float*)d_in[8];
    const float* dense1_bias   = (const float*)d_in[9];
    const float* out_kernel    = (const float*)d_in[10];
    const float* out_bias      = (const float*)d_in[11];

    static bool attr_done = false;
    if (!attr_done) {
        cudaFuncSetAttribute(moon_gemm_mma,
                             cudaFuncAttributeMaxDynamicSharedMemorySize,
                             2 * STAGE_BYTES);
        attr_done = true;
    }

    moon_setup<<<72, 256>>>(beta_kernel, beta_bias, gamma_kernel, out_kernel);

    moon_phase1<<<296, 256>>>(r, r_nb, ee_scales, ee_kernel, ee_bias,
                              dense1_kernel, dense1_bias);

    dim3 gridB(DD / 64, NROWS / 128);
    moon_gemm_mma<<<gridB, 256, 2 * STAGE_BYTES>>>(out_bias, (float*)d_out);
}

// round 16
// speedup vs baseline: 1.1312x; 1.1292x over previous
#include <cuda_runtime.h>
#include <cuda_bf16.h>
#include <cuda_fp16.h>
#include <math.h>
#include <stdint.h>

constexpr int NNB  = 32;
constexpr int F0   = 16;
constexpr int DD   = 256;
constexpr int NROWS = 8192;       // B*E
constexpr int NPAIRS = NROWS / 2;
constexpr int ZS   = 40;          // smem z row stride in fp16 (80B, conflict-free frags)
constexpr int WGS  = 36;          // smem WGT row stride in fp16 (72B)

// A (phase1 result) bf16 hi/lo, row-major [8192][256]  (gemm unchanged)
__device__ __align__(16) __nv_bfloat16 g_Ah[NROWS * DD];
__device__ __align__(16) __nv_bfloat16 g_Al[NROWS * DD];
// out_kernel^T bf16 hi/lo, row-major [n=256][k=256]
__device__ __align__(16) __nv_bfloat16 g_WTh[DD * DD];
__device__ __align__(16) __nv_bfloat16 g_WTl[DD * DD];
// WG^T fp16 hi/lo, [d=256][c=32] (c>=25 zero)
__device__ __align__(16) __half g_WGTh[DD * 32];
__device__ __align__(16) __half g_WGTl[DD * 32];

// ---------------- helpers ----------------
typedef unsigned long long ull;
__device__ __forceinline__ ull pack2(float lo, float hi) {
    ull r;
    asm("mov.b64 %0, {%1, %2};" : "=l"(r) : "f"(lo), "f"(hi));
    return r;
}
__device__ __forceinline__ ull fma2(ull a, ull b, ull c) {
    ull d;
    asm("fma.rn.f32x2 %0, %1, %2, %3;" : "=l"(d) : "l"(a), "l"(b), "l"(c));
    return d;
}
__device__ __forceinline__ ull mul2(ull a, ull b) {
    ull d;
    asm("mul.rn.f32x2 %0, %1, %2;" : "=l"(d) : "l"(a), "l"(b));
    return d;
}
__device__ __forceinline__ float2 unpack2(ull v) {
    float2 r;
    asm("mov.b64 {%0, %1}, %2;" : "=f"(r.x), "=f"(r.y) : "l"(v));
    return r;
}
__device__ __forceinline__ float tanh_approx(float x) {
    float y;
    asm("tanh.approx.f32 %0, %1;" : "=f"(y) : "f"(x));
    return y;
}
__device__ __forceinline__ uint32_t smem_u32(const void* p) {
    uint32_t a;
    asm("{ .reg .u64 t; cvta.to.shared.u64 t, %1; cvt.u32.u64 %0, t; }" : "=r"(a) : "l"(p));
    return a;
}

// bf16 MMA (gemm)
#define MMA16816(d, a, b0v, b1v) \
    asm volatile("mma.sync.aligned.m16n8k16.row.col.f32.bf16.bf16.f32 " \
        "{%0,%1,%2,%3}, {%4,%5,%6,%7}, {%8,%9}, {%0,%1,%2,%3};" \
        : "+f"((d)[0]), "+f"((d)[1]), "+f"((d)[2]), "+f"((d)[3]) \
        : "r"((a)[0]), "r"((a)[1]), "r"((a)[2]), "r"((a)[3]), "r"(b0v), "r"(b1v))

// fp16 MMA (phase1 z-contraction)
#define MMA16816H(d, a, b0v, b1v) \
    asm volatile("mma.sync.aligned.m16n8k16.row.col.f32.f16.f16.f32 " \
        "{%0,%1,%2,%3}, {%4,%5,%6,%7}, {%8,%9}, {%0,%1,%2,%3};" \
        : "+f"((d)[0]), "+f"((d)[1]), "+f"((d)[2]), "+f"((d)[3]) \
        : "r"((a)[0]), "r"((a)[1]), "r"((a)[2]), "r"((a)[3]), "r"(b0v), "r"(b1v))

#define CP16(daddr, sptr) \
    asm volatile("cp.async.ca.shared.global [%0], [%1], 16;" \
                 :: "r"(daddr), "l"(sptr) : "memory")

// ---------------------------------------------------------------------------
// Setup: blocks 0..63: 32x32 tiled transpose of W (bf16 hi/lo, both coalesced).
//        blocks 64..71: WG fold -> fp16 hi/lo, fully unrolled (MLP=32).
// ---------------------------------------------------------------------------
__global__ void moon_setup(const float* __restrict__ Wb,   // [24,32]
                           const float* __restrict__ bb,   // [32]
                           const float* __restrict__ G,    // [32,256]
                           const float* __restrict__ W)    // [256,256]
{
    const int b = blockIdx.x;
    const int t = threadIdx.x;
    if (b < 64) {
        __shared__ float tile[32][33];
        const int bi = b >> 3;
        const int bj = b & 7;
        const int r0 = t >> 5;
        const int c  = t & 31;
        #pragma unroll
        for (int i = 0; i < 4; i++) {
            const int kr = r0 * 4 + i;
            tile[kr][c] = W[(bi * 32 + kr) * DD + bj * 32 + c];
        }
        __syncthreads();
        #pragma unroll
        for (int i = 0; i < 4; i++) {
            const int nr = r0 * 4 + i;
            const float w = tile[c][nr];
            const __nv_bfloat16 h = __float2bfloat16(w);
            const int n = bj * 32 + nr;
            const int k = bi * 32 + c;
            g_WTh[n * DD + k] = h;
            g_WTl[n * DD + k] = __float2bfloat16(w - __bfloat162float(h));
        }
    } else {
        const int b2 = b - 64;
        const int n  = b2 * 32 + (t & 31);
        const int cg = t >> 5;
        float a[4] = {0.0f, 0.0f, 0.0f, 0.0f};
        #pragma unroll
        for (int k = 0; k < 32; k++) {
            const float g = G[k * DD + n];
            #pragma unroll
            for (int q = 0; q < 4; q++) {
                const int c = cg * 4 + q;
                const float wv = (c < 24) ? Wb[c * 32 + k]
                                          : ((c == 24) ? bb[k] : 0.0f);
                a[q] = fmaf(wv, g, a[q]);
            }
        }
        #pragma unroll
        for (int q = 0; q < 4; q++) {
            const int c = cg * 4 + q;
            const __half h = __float2half(a[q]);
            g_WGTh[n * 32 + c] = h;
            g_WGTl[n * 32 + c] = __float2half(a[q] - __half2float(h));
        }
    }
}

// ---------------------------------------------------------------------------
// Phase 1 (PERSISTENT, 296 CTAs): z single fp16, WGT fp16 hi/lo -> 2 MMA chains.
// ---------------------------------------------------------------------------
__global__ __launch_bounds__(256, 2) void moon_phase1(
    const float* __restrict__ r,
    const float* __restrict__ r_nb,
    const float* __restrict__ ee_scales,
    const float* __restrict__ ee_kernel,
    const float* __restrict__ ee_bias,
    const float* __restrict__ dense1_kernel,
    const float* __restrict__ dense1_bias)
{
    __shared__ __align__(16) __half sZ[2][NNB][ZS];               // 5 KB
    __shared__ __align__(16) float s_inp[2][NNB][4];              // 1 KB
    __shared__ __align__(16) float s_w[4][DD];                    // 4 KB
    __shared__ __align__(16) float s_b[DD];                       // 1 KB
    __shared__ __align__(16) __half sWGh[DD * WGS];               // 18 KB
    __shared__ __align__(16) __half sWGl[DD * WGS];               // 18 KB

    const int t = threadIdx.x;

    // ---- one-time staging ----
    #pragma unroll
    for (int i = 0; i < 4; i++) ((float*)s_w)[t + i * 256] = dense1_kernel[t + i * 256];
    s_b[t] = dense1_bias[t];
    {
        const uint2* srcH = (const uint2*)&g_WGTh[t * 32];
        const uint2* srcL = (const uint2*)&g_WGTl[t * 32];
        uint2* dstH = (uint2*)&sWGh[t * WGS];
        uint2* dstL = (uint2*)&sWGl[t * WGS];
        #pragma unroll
        for (int i = 0; i < 8; i++) { dstH[i] = srcH[i]; dstL[i] = srcL[i]; }
    }

    const int half = t >> 7;
    const int u    = t & 127;
    const int n1   = u >> 2;
    const int j1   = u & 3;

    const int lane = t & 31;
    const int wid  = t >> 5;
    const int gid  = lane >> 2;
    const int tig  = lane & 3;
    const int prow = wid >> 2;
    const int warpN = (wid & 3) * 64;
    const ull K05 = pack2(0.5f, 0.5f);

    __syncthreads();

    for (int pair = blockIdx.x; pair < NPAIRS; pair += gridDim.x) {
        const long row = (long)pair * 2 + half;

        // ---------------- stage 1 ----------------
        {
            const int n = n1, j = j1;
            const float rx = r[row * 3 + 0];
            const float ry = r[row * 3 + 1];
            const float rz = r[row * 3 + 2];
            const float* nb = r_nb + (row * NNB + n) * 3;
            const float dx = nb[0] - rx;
            const float dy = nb[1] - ry;
            const float dz = nb[2] - rz;
            const float dist = sqrtf(dx * dx + dy * dy + dz * dz);

            const float x = dist * 0.2f;
            const float fcut = (x < 1.0f)
                ? 0.5f * (__cosf(3.14159265358979323846f * x) + 1.0f)
                : 0.0f;

            #pragma unroll
            for (int kk = 0; kk < 4; kk++) {
                const int k = j * 4 + kk;
                float a = ee_bias[k]
                        + dist * ee_kernel[0 * F0 + k]
                        + dx   * ee_kernel[1 * F0 + k]
                        + dy   * ee_kernel[2 * F0 + k]
                        + dz   * ee_kernel[3 * F0 + k];
                sZ[half][n][k] = __float2half(tanh_approx(a) * fcut);
            }
            #pragma unroll
            for (int m = 0; m < 2; m++) {
                const int e = j * 2 + m;
                const float q = __fdividef(dist, ee_scales[e]);
                sZ[half][n][F0 + e] = __float2half(__expf(-q * q) * fcut);
            }
            if (j == 0) {
                *(uint4*)&sZ[half][n][24] = make_uint4(0u, 0u, 0u, 0u);
                sZ[half][n][24] = __float2half(fcut);   // bias column of WG

                const float lp = __logf(1.0f + dist);
                const float sc = __fdividef(lp, dist);
                s_inp[half][n][0] = lp;
                s_inp[half][n][1] = dx * sc;
                s_inp[half][n][2] = dy * sc;
                s_inp[half][n][3] = dz * sc;
            }
        }
        __syncthreads();

        // ---------------- stage 2 ----------------
        {
            const long grow = (long)pair * 2 + prow;

            // A fragments (z fp16, single)
            uint32_t az[2][2][4];
            #pragma unroll
            for (int mf = 0; mf < 2; mf++)
                #pragma unroll
                for (int kf = 0; kf < 2; kf++) {
                    const int na = mf * 16 + gid;
                    const int nb2 = na + 8;
                    const int k  = kf * 16 + 2 * tig;
                    az[mf][kf][0] = *(const uint32_t*)&sZ[prow][na][k];
                    az[mf][kf][1] = *(const uint32_t*)&sZ[prow][nb2][k];
                    az[mf][kf][2] = *(const uint32_t*)&sZ[prow][na][k + 8];
                    az[mf][kf][3] = *(const uint32_t*)&sZ[prow][nb2][k + 8];
                }

            // hoisted ip packs
            ull ipp[4][4];
            #pragma unroll
            for (int it = 0; it < 4; it++) {
                const int n = ((it >> 1) * 16) + ((it & 1) * 8) + gid;
                const float4 ip = *(const float4*)s_inp[prow][n];
                ipp[it][0] = pack2(ip.x, ip.x);
                ipp[it][1] = pack2(ip.y, ip.y);
                ipp[it][2] = pack2(ip.z, ip.z);
                ipp[it][3] = pack2(ip.w, ip.w);
            }

            #pragma unroll
            for (int hn = 0; hn < 2; hn++) {
                float acc[2][4][4];
                #pragma unroll
                for (int mf = 0; mf < 2; mf++)
                    #pragma unroll
                    for (int nf = 0; nf < 4; nf++)
                        #pragma unroll
                        for (int c = 0; c < 4; c++) acc[mf][nf][c] = 0.0f;

                #pragma unroll
                for (int nf = 0; nf < 4; nf++) {
                    const int ncol = warpN + hn * 32 + nf * 8 + gid;
                    const __half* ph = &sWGh[ncol * WGS];
                    const __half* pl = &sWGl[ncol * WGS];
                    #pragma unroll
                    for (int kf = 0; kf < 2; kf++) {
                        const uint32_t bh0 = *(const uint32_t*)&ph[kf * 16 + 2 * tig];
                        const uint32_t bh1 = *(const uint32_t*)&ph[kf * 16 + 8 + 2 * tig];
                        const uint32_t bl0 = *(const uint32_t*)&pl[kf * 16 + 2 * tig];
                        const uint32_t bl1 = *(const uint32_t*)&pl[kf * 16 + 8 + 2 * tig];
                        MMA16816H(acc[0][nf], az[0][kf], bh0, bh1);
                        MMA16816H(acc[1][nf], az[1][kf], bh0, bh1);
                        MMA16816H(acc[0][nf], az[0][kf], bl0, bl1);
                        MMA16816H(acc[1][nf], az[1][kf], bl0, bl1);
                    }
                }

                // packed product-reduce, immediate shfl per nf
                #pragma unroll
                for (int nf = 0; nf < 4; nf++) {
                    const int d0 = warpN + hn * 32 + nf * 8 + 2 * tig;
                    const ull wp0 = *(const ull*)&s_w[0][d0];
                    const ull wp1 = *(const ull*)&s_w[1][d0];
                    const ull wp2 = *(const ull*)&s_w[2][d0];
                    const ull wp3 = *(const ull*)&s_w[3][d0];
                    const ull bp  = *(const ull*)&s_b[d0];

                    ull s2 = 0ull;
                    #pragma unroll
                    for (int it = 0; it < 4; it++) {
                        ull pre2 = fma2(ipp[it][0], wp0,
                                   fma2(ipp[it][1], wp1,
                                   fma2(ipp[it][2], wp2,
                                   fma2(ipp[it][3], wp3, bp))));
                        const ull ph2 = mul2(pre2, K05);
                        const float2 pu = unpack2(ph2);
                        const ull tp = pack2(tanh_approx(pu.x), tanh_approx(pu.y));
                        const ull sg = fma2(tp, K05, K05);
                        const ull feat2 = mul2(pre2, sg);
                        const ull gam2 = pack2(acc[it >> 1][nf][(it & 1) * 2],
                                               acc[it >> 1][nf][(it & 1) * 2 + 1]);
                        s2 = fma2(feat2, gam2, s2);
                    }

                    float2 sv = unpack2(s2);
                    sv.x += __shfl_xor_sync(0xffffffffu, sv.x, 4);
                    sv.y += __shfl_xor_sync(0xffffffffu, sv.y, 4);
                    sv.x += __shfl_xor_sync(0xffffffffu, sv.x, 8);
                    sv.y += __shfl_xor_sync(0xffffffffu, sv.y, 8);
                    sv.x += __shfl_xor_sync(0xffffffffu, sv.x, 16);
                    sv.y += __shfl_xor_sync(0xffffffffu, sv.y, 16);

                    if (gid == 0) {
                        const __nv_bfloat16 h0 = __float2bfloat16(sv.x);
                        const __nv_bfloat16 h1 = __float2bfloat16(sv.y);
                        *(__nv_bfloat162*)&g_Ah[grow * DD + d0] = __halves2bfloat162(h0, h1);
                        const __nv_bfloat16 l0 = __float2bfloat16(sv.x - __bfloat162float(h0));
                        const __nv_bfloat16 l1 = __float2bfloat16(sv.y - __bfloat162float(h1));
                        *(__nv_bfloat162*)&g_Al[grow * DD + d0] = __halves2bfloat162(l0, l1);
                    }
                }
            }
        }
        __syncthreads();
    }
}

// ---------------------------------------------------------------------------
// Kernel B (r13-proven): Y = silu(A @ W + bias), 3-chain compensated bf16,
// cp.async 2-stage pipelined K chunks.  BM=128, BN=128, KS=88.
// ---------------------------------------------------------------------------
constexpr int KS = 88;
constexpr int TILE_BYTES = 128 * KS * 2;       // 22528
constexpr int STAGE_BYTES = 4 * TILE_BYTES;    // 90112

__global__ __launch_bounds__(256) void moon_gemm_mma(
    const float* __restrict__ bias, float* __restrict__ Y)
{
    extern __shared__ __align__(16) char smem[];

    const int t    = threadIdx.x;
    const int lane = t & 31;
    const int wid  = t >> 5;
    const int gid  = lane >> 2;
    const int tig  = lane & 3;
    const int warp_m = wid & 3;
    const int warp_n = wid >> 2;
    const int ct   = blockIdx.x;
    const int rowT = blockIdx.y;

    const uint32_t sbase = smem_u32(smem);

    float acc[2][8][4];
    #pragma unroll
    for (int mf = 0; mf < 2; mf++)
        #pragma unroll
        for (int j = 0; j < 8; j++)
            #pragma unroll
            for (int c = 0; c < 4; c++) acc[mf][j][c] = 0.0f;

    const size_t aBase = (size_t)(rowT * 128) * DD;
    const size_t bBase = (size_t)(ct * 128) * DD;

    #define ISSUE_STAGE(kc, sidx) do { \
        const uint32_t sb_ = sbase + (sidx) * STAGE_BYTES; \
        _Pragma("unroll") \
        for (int i_ = 0; i_ < 4; i_++) { \
            const int lin_ = t + i_ * 256; \
            const int rr_  = lin_ >> 3; \
            const int kq_  = (lin_ & 7) * 8; \
            const size_t goff_ = (size_t)rr_ * DD + (kc) * 64 + kq_; \
            const uint32_t so_ = (uint32_t)(rr_ * KS + kq_) * 2; \
            CP16(sb_ + so_,                  &g_Ah[aBase + goff_]); \
            CP16(sb_ + TILE_BYTES + so_,     &g_Al[aBase + goff_]); \
            CP16(sb_ + 2 * TILE_BYTES + so_, &g_WTh[bBase + goff_]); \
            CP16(sb_ + 3 * TILE_BYTES + so_, &g_WTl[bBase + goff_]); \
        } \
        asm volatile("cp.async.commit_group;" ::: "memory"); \
    } while (0)

    ISSUE_STAGE(0, 0);
    ISSUE_STAGE(1, 1);

    #pragma unroll
    for (int kc = 0; kc < 4; kc++) {
        if (kc < 3) asm volatile("cp.async.wait_group 1;" ::: "memory");
        else        asm volatile("cp.async.wait_group 0;" ::: "memory");
        __syncthreads();

        const int sidx = kc & 1;
        const __nv_bfloat16* sAh = (const __nv_bfloat16*)(smem + sidx * STAGE_BYTES);
        const __nv_bfloat16* sAl = (const __nv_bfloat16*)(smem + sidx * STAGE_BYTES + TILE_BYTES);
        const __nv_bfloat16* sBh = (const __nv_bfloat16*)(smem + sidx * STAGE_BYTES + 2 * TILE_BYTES);
        const __nv_bfloat16* sBl = (const __nv_bfloat16*)(smem + sidx * STAGE_BYTES + 3 * TILE_BYTES);

        #pragma unroll
        for (int k16 = 0; k16 < 4; k16++) {
            const int koff = k16 * 16;
            uint32_t ah[2][4], al[2][4];
            #pragma unroll
            for (int mf = 0; mf < 2; mf++) {
                const int mb = warp_m * 32 + mf * 16;
                const int r0 = (mb + gid) * KS + koff + 2 * tig;
                const int r1 = (mb + 8 + gid) * KS + koff + 2 * tig;
                ah[mf][0] = *(const uint32_t*)&sAh[r0];
                ah[mf][1] = *(const uint32_t*)&sAh[r1];
                ah[mf][2] = *(const uint32_t*)&sAh[r0 + 8];
                ah[mf][3] = *(const uint32_t*)&sAh[r1 + 8];
                al[mf][0] = *(const uint32_t*)&sAl[r0];
                al[mf][1] = *(const uint32_t*)&sAl[r1];
                al[mf][2] = *(const uint32_t*)&sAl[r0 + 8];
                al[mf][3] = *(const uint32_t*)&sAl[r1 + 8];
            }
            #pragma unroll
            for (int j = 0; j < 8; j++) {
                const int nb = (warp_n * 64 + j * 8 + gid) * KS + koff + 2 * tig;
                const uint32_t bh0 = *(const uint32_t*)&sBh[nb];
                const uint32_t bh1 = *(const uint32_t*)&sBh[nb + 8];
                const uint32_t bl0 = *(const uint32_t*)&sBl[nb];
                const uint32_t bl1 = *(const uint32_t*)&sBl[nb + 8];
                #pragma unroll
                for (int mf = 0; mf < 2; mf++) {
                    MMA16816(acc[mf][j], ah[mf], bh0, bh1);
                    MMA16816(acc[mf][j], ah[mf], bl0, bl1);
                    MMA16816(acc[mf][j], al[mf], bh0, bh1);
                }
            }
        }
        __syncthreads();
        if (kc < 2) ISSUE_STAGE(kc + 2, sidx);
    }

    #pragma unroll
    for (int j = 0; j < 8; j++) {
        const int col = ct * 128 + warp_n * 64 + j * 8 + 2 * tig;
        const float2 bb = *(const float2*)&bias[col];
        #pragma unroll
        for (int mf = 0; mf < 2; mf++) {
            const long row0 = rowT * 128 + warp_m * 32 + mf * 16 + gid;
            float v0 = acc[mf][j][0] + bb.x;
            float v1 = acc[mf][j][1] + bb.y;
            float v2 = acc[mf][j][2] + bb.x;
            float v3 = acc[mf][j][3] + bb.y;
            float2 o0, o1;
            o0.x = __fdividef(v0, 1.0f + __expf(-v0));
            o0.y = __fdividef(v1, 1.0f + __expf(-v1));
            o1.x = __fdividef(v2, 1.0f + __expf(-v2));
            o1.y = __fdividef(v3, 1.0f + __expf(-v3));
            *(float2*)&Y[row0 * DD + col]       = o0;
            *(float2*)&Y[(row0 + 8) * DD + col] = o1;
        }
    }
}

// ---------------------------------------------------------------------------
extern "C" void kernel_launch(void* const* d_in, const int* in_sizes, int n_in,
                              void* d_out, int out_size)
{
    const float* r             = (const float*)d_in[0];
    const float* r_nb          = (const float*)d_in[1];
    const float* ee_scales     = (const float*)d_in[2];
    const float* ee_kernel     = (const float*)d_in[3];
    const float* ee_bias       = (const float*)d_in[4];
    const float* beta_kernel   = (const float*)d_in[5];
    const float* beta_bias     = (const float*)d_in[6];
    const float* gamma_kernel  = (const float*)d_in[7];
    const float* dense1_kernel = (const float*)d_in[8];
    const float* dense1_bias   = (const float*)d_in[9];
    const float* out_kernel    = (const float*)d_in[10];
    const float* out_bias      = (const float*)d_in[11];

    static bool attr_done = false;
    if (!attr_done) {
        cudaFuncSetAttribute(moon_gemm_mma,
                             cudaFuncAttributeMaxDynamicSharedMemorySize,
                             2 * STAGE_BYTES);
        attr_done = true;
    }

    moon_setup<<<72, 256>>>(beta_kernel, beta_bias, gamma_kernel, out_kernel);

    moon_phase1<<<296, 256>>>(r, r_nb, ee_scales, ee_kernel, ee_bias,
                              dense1_kernel, dense1_bias);

    dim3 gridB(2, NROWS / 128);
    moon_gemm_mma<<<gridB, 256, 2 * STAGE_BYTES>>>(out_bias, (float*)d_out);
}